// round 15
// baseline (speedup 1.0000x reference)
#include <cuda_runtime.h>
#include <stdint.h>

// ============================================================================
// One-sweep speculative radix-select threshold kernel (v15 = R14 + 2x-unrolled
// pass1 loads (MLP=2/thread) + wider tail grid).
//
// thresh = rank-mf (0-based) entry of the descending sort of all inputs.
// out[i] = x[i] < thresh ? 0 : x[i].
//
// Key map (order-preserving): key = u ^ (sign ? 0xFFFFFFFF : 0x80000000).
//
// THREE launches:
//  pass1:  read all (2 independent uint4 loads in flight per thread), write
//          out thresholded at 1.9375. Candidates allocated into per-WARP
//          slices via per-warp smem atomic counters, smem 4096-bin hist of
//          key>>20. Last block decides mode + selects digit1 (12 bits).
//  round2: warp-per-slice, register-resident keys, warp-scan + one global
//          atomic per block dense compaction, smem hist bits[19:8].
//          Last block selects digit2 (-> 24-bit prefix).
//  tail:   scan dense buffer; zero below 24-bit prefix; collect matched
//          stragglers + 256-bin hist of bits[7:0]; last block selects final
//          digit -> exact key, zeroes stragglers below it.
//          Fallback (mode 1): full-read hist phases + rewrite, gated.
//          Trivial (mode 2): thresh=0 rewrite.
// ============================================================================

#define NB     1024
#define NT     256
#define NWARP  (NB * NT / 32)     // 8192
#define SLICE  256u
#define CBUF_CAP (NWARP * SLICE)  // 2M entries
#define MCAP   16384u
#define FTH    1.9375f
#define HBINS  4096
#define TGRID  256

__device__ unsigned g_h[HBINS];
__device__ unsigned g_key[NWARP * SLICE];   // 8 MB
__device__ unsigned g_idx[NWARP * SLICE];   // 8 MB
__device__ unsigned g_ck[CBUF_CAP];         // 8 MB dense in-bin keys
__device__ unsigned g_ci[CBUF_CAP];         // 8 MB dense in-bin idx
__device__ unsigned g_mk[MCAP];             // straggler keys
__device__ unsigned g_mi[MCAP];             // straggler idx
__device__ unsigned g_warpcnt[NWARP];
__device__ unsigned g_ctr[8];
__device__ unsigned g_go[8];
__device__ unsigned g_cand_cnt;
__device__ unsigned g_mcnt;
__device__ unsigned g_nscratch;
__device__ int      g_mode;       // 0=spec, 1=fallback, 2=trivial
__device__ int      g_overflow;
__device__ unsigned g_pref;       // accumulated digit prefix (right-aligned)
__device__ unsigned g_rank;       // residual rank
__device__ unsigned g_key32;      // final exact key
__device__ float    g_thresh;

__device__ __forceinline__ unsigned fmap_u(unsigned u) {
    return u ^ ((unsigned)((int)u >> 31) | 0x80000000u);
}
__device__ __forceinline__ float finv_map(unsigned k) {
    unsigned u = (k & 0x80000000u) ? (k ^ 0x80000000u) : ~k;
    return __uint_as_float(u);
}

// Block-cooperative descending rank-select over g_h[0..nbins). 256 threads.
__device__ void select_digitN(int nbins, int append_bits, int final_stage) {
    __shared__ unsigned tsum[256];
    __shared__ unsigned wsum[8];
    int per = nbins >> 8;
    unsigned s = 0;
    int base = threadIdx.x * per;
    for (int j = 0; j < per; j++) s += g_h[base + j];
    tsum[threadIdx.x] = s;
    unsigned ws = s;
    ws += __shfl_xor_sync(0xFFFFFFFFu, ws, 16);
    ws += __shfl_xor_sync(0xFFFFFFFFu, ws, 8);
    ws += __shfl_xor_sync(0xFFFFFFFFu, ws, 4);
    ws += __shfl_xor_sync(0xFFFFFFFFu, ws, 2);
    ws += __shfl_xor_sync(0xFFFFFFFFu, ws, 1);
    if ((threadIdx.x & 31) == 0) wsum[threadIdx.x >> 5] = ws;
    __syncthreads();
    if (threadIdx.x == 0) {
        unsigned r = g_rank;
        int w = 7;
        for (; w > 0; w--) { if (r < wsum[w]) break; r -= wsum[w]; }
        int t = 31;
        for (; t > 0; t--) { unsigned c = tsum[w * 32 + t]; if (r < c) break; r -= c; }
        int b = (w * 32 + t) * per;
        int j = per - 1;
        for (; j > 0; j--) { unsigned c = g_h[b + j]; if (r < c) break; r -= c; }
        unsigned d = (unsigned)(b + j);
        unsigned p = (g_pref << append_bits) | d;
        g_pref = p;
        g_rank = r;
        if (final_stage) { g_key32 = p; g_thresh = finv_map(p); }
    }
    __syncthreads();
    for (int j = threadIdx.x; j < nbins; j += 256) g_h[j] = 0;
    __syncthreads();
}

// Spin barrier used ONLY by the fallback path (mode 1).
__device__ void fb_sync(int ph, int nbins, int append_bits, int fin) {
    __threadfence();
    __syncthreads();
    __shared__ unsigned slast;
    if (threadIdx.x == 0)
        slast = (atomicAdd(&g_ctr[ph], 1u) == gridDim.x - 1u) ? 1u : 0u;
    __syncthreads();
    if (slast) {
        select_digitN(nbins, append_bits, fin);
        __threadfence();
        if (threadIdx.x == 0) *(volatile unsigned*)&g_go[ph] = 1u;
    } else {
        if (threadIdx.x == 0)
            while (*(volatile unsigned*)&g_go[ph] == 0u) __nanosleep(64);
        __syncthreads();
        __threadfence();
    }
    __syncthreads();
}

// ---------------------------------------------------------------------------
__global__ void __launch_bounds__(NT) k_pass1(
        const uint4* __restrict__ a0, int n0,
        const uint4* __restrict__ a1, int n1,
        const uint4* __restrict__ a2, int n2,
        uint4* __restrict__ out,
        const int* mf_ptr, int host_mf, long long ntot) {
    __shared__ unsigned shh[HBINS];
    __shared__ unsigned swo[NT / 32];     // per-warp slice write cursors
    for (int j = threadIdx.x; j < HBINS; j += NT) shh[j] = 0;
    if (threadIdx.x < NT / 32) swo[threadIdx.x] = 0;
    __syncthreads();

    int tid = blockIdx.x * blockDim.x + threadIdx.x;
    int stride = gridDim.x * blockDim.x;
    unsigned wip = threadIdx.x >> 5;
    unsigned gw = (unsigned)tid >> 5;
    unsigned sbase = gw * SLICE;
    bool ovf = false;

#define P1_EMIT(KU, IB, P)                                                    \
    do {                                                                      \
        unsigned kk = fmap_u(KU);                                             \
        g_key[P] = kk; g_idx[P] = (IB);                                       \
        atomicAdd(&shh[kk >> 20], 1u);                                        \
        (P)++;                                                                \
    } while (0)

#define P1_PROC(V, I, OUTP, EO)                                               \
    do {                                                                      \
        bool c0 = !(__uint_as_float((V).x) < FTH);                            \
        bool c1 = !(__uint_as_float((V).y) < FTH);                            \
        bool c2 = !(__uint_as_float((V).z) < FTH);                            \
        bool c3 = !(__uint_as_float((V).w) < FTH);                            \
        uint4 w;                                                              \
        w.x = c0 ? (V).x : 0u;  w.y = c1 ? (V).y : 0u;                        \
        w.z = c2 ? (V).z : 0u;  w.w = c3 ? (V).w : 0u;                        \
        __stcs(&(OUTP)[I], w);                                                \
        unsigned cnt = (unsigned)c0 + (unsigned)c1 +                          \
                       (unsigned)c2 + (unsigned)c3;                           \
        if (cnt) {                                                            \
            unsigned off = atomicAdd(&swo[wip], cnt);                         \
            if (off + cnt <= SLICE) {                                         \
                unsigned p = sbase + off;                                     \
                unsigned ib = (EO) + 4u * (unsigned)(I);                      \
                if (c0) P1_EMIT((V).x, ib, p);                                \
                if (c1) P1_EMIT((V).y, ib + 1u, p);                           \
                if (c2) P1_EMIT((V).z, ib + 2u, p);                           \
                if (c3) P1_EMIT((V).w, ib + 3u, p);                           \
            } else {                                                          \
                ovf = true;                                                   \
            }                                                                 \
        }                                                                     \
    } while (0)

#define P1_BODY(ARR, N, OUTP, EO)                                             \
    {                                                                         \
        int i = tid;                                                          \
        for (; i + stride < (N); i += 2 * stride) {                           \
            uint4 v1 = __ldcs(&(ARR)[i]);                                     \
            uint4 v2 = __ldcs(&(ARR)[i + stride]);                            \
            P1_PROC(v1, i, OUTP, EO);                                         \
            P1_PROC(v2, i + stride, OUTP, EO);                                \
        }                                                                     \
        if (i < (N)) {                                                        \
            uint4 v1 = __ldcs(&(ARR)[i]);                                     \
            P1_PROC(v1, i, OUTP, EO);                                         \
        }                                                                     \
    }
    P1_BODY(a0, n0, out, 0u)
    P1_BODY(a1, n1, out + n0, 4u * (unsigned)n0)
    P1_BODY(a2, n2, out + n0 + n1, 4u * (unsigned)(n0 + n1))
#undef P1_BODY
#undef P1_PROC
#undef P1_EMIT

    if (ovf) g_overflow = 1;
    __syncthreads();
    if ((threadIdx.x & 31u) == 0) {
        unsigned wo = swo[wip];
        g_warpcnt[gw] = (wo > SLICE) ? SLICE : wo;
        atomicAdd(&g_nscratch, wo);
    }
    for (int j = threadIdx.x; j < HBINS; j += NT)
        if (shh[j]) atomicAdd(&g_h[j], shh[j]);
    __threadfence();

    __shared__ unsigned islast;
    if (threadIdx.x == 0)
        islast = (atomicAdd(&g_ctr[0], 1u) == gridDim.x - 1u) ? 1u : 0u;
    __syncthreads();
    if (!islast) return;

    __shared__ int smode;
    if (threadIdx.x == 0) {
        long long mf = (mf_ptr != nullptr) ? (long long)(*mf_ptr)
                                           : (long long)host_mf;
        if (mf < 0) mf = 0;
        int mode;
        if (mf >= ntot)                                        mode = 2;
        else if (g_overflow || (long long)g_nscratch < mf + 1) mode = 1;
        else                                                   mode = 0;
        g_mode = mode;
        smode = mode;
        g_rank = (unsigned)mf;
        g_pref = 0;
        if (mode == 2) g_thresh = 0.0f;
    }
    __syncthreads();
    if (smode == 0) {
        select_digitN(HBINS, 12, 0);
    } else {
        for (int j = threadIdx.x; j < HBINS; j += NT) g_h[j] = 0;
    }
}

// ---------------------------------------------------------------------------
// round2: warp w handles slice w. Single pass, register-resident keys
// (2x uint4 loads cover all SLICE=256 entries), one global atomic per block.
__global__ void __launch_bounds__(NT) k_round2(float4* __restrict__ out) {
    __shared__ unsigned shh[HBINS];
    __shared__ unsigned wcnt_s[NT / 32];
    __shared__ unsigned wbase_s[NT / 32];
    int mode = g_mode;
    if (mode == 0) {
        for (int j = threadIdx.x; j < HBINS; j += NT) shh[j] = 0;
        __syncthreads();

        unsigned lane = threadIdx.x & 31u;
        unsigned wip = threadIdx.x >> 5;
        unsigned w = (blockIdx.x * blockDim.x + threadIdx.x) >> 5;
        const unsigned pref12 = g_pref;
        float* of = (float*)out;

        unsigned cnt = g_warpcnt[w];
        if (cnt > SLICE) cnt = SLICE;
        const uint4* kp4 = (const uint4*)&g_key[w * SLICE];
        const unsigned* ip = &g_idx[w * SLICE];

        uint4 ka = kp4[lane];
        uint4 kb = kp4[lane + 32];
        unsigned keys[8] = {ka.x, ka.y, ka.z, ka.w, kb.x, kb.y, kb.z, kb.w};

        unsigned mc = 0, mmask = 0;
#pragma unroll
        for (int r = 0; r < 8; r++) {
            unsigned e = (r < 4) ? (4u * lane + (unsigned)r)
                                 : (128u + 4u * lane + (unsigned)(r - 4));
            bool valid = e < cnt;
            unsigned p12 = keys[r] >> 20;
            if (valid && p12 < pref12) of[ip[e]] = 0.0f;
            if (valid && p12 == pref12) { mc++; mmask |= 1u << r; }
        }

        unsigned incl = mc;
#pragma unroll
        for (int o = 1; o < 32; o <<= 1) {
            unsigned t = __shfl_up_sync(0xFFFFFFFFu, incl, o);
            if (lane >= (unsigned)o) incl += t;
        }
        unsigned wtot = __shfl_sync(0xFFFFFFFFu, incl, 31);
        unsigned texcl = incl - mc;
        if (lane == 0) wcnt_s[wip] = wtot;
        __syncthreads();
        if (threadIdx.x == 0) {
            unsigned tot = 0, b[NT / 32];
            for (int q = 0; q < NT / 32; q++) { b[q] = tot; tot += wcnt_s[q]; }
            unsigned base = tot ? atomicAdd(&g_cand_cnt, tot) : 0u;
            for (int q = 0; q < NT / 32; q++) wbase_s[q] = base + b[q];
        }
        __syncthreads();
        unsigned pos = wbase_s[wip] + texcl;

#pragma unroll
        for (int r = 0; r < 8; r++) {
            if ((mmask >> r) & 1u) {
                unsigned e = (r < 4) ? (4u * lane + (unsigned)r)
                                     : (128u + 4u * lane + (unsigned)(r - 4));
                if (pos < CBUF_CAP) {
                    g_ck[pos] = keys[r];
                    g_ci[pos] = ip[e];
                }
                atomicAdd(&shh[(keys[r] >> 8) & 4095u], 1u);
                pos++;
            }
        }
        __syncthreads();
        for (int j = threadIdx.x; j < HBINS; j += NT)
            if (shh[j]) atomicAdd(&g_h[j], shh[j]);
    }
    __threadfence();
    __shared__ unsigned islast;
    if (threadIdx.x == 0)
        islast = (atomicAdd(&g_ctr[1], 1u) == gridDim.x - 1u) ? 1u : 0u;
    __syncthreads();
    if (!islast) return;

    if (threadIdx.x == 0) {
        g_ctr[0] = 0; g_nscratch = 0; g_overflow = 0;
    }
    if (mode == 0) select_digitN(HBINS, 12, 0);   // -> 24-bit prefix
}

// ---------------------------------------------------------------------------
__global__ void __launch_bounds__(NT) k_tail(
        const uint4* __restrict__ a0, int n0,
        const uint4* __restrict__ a1, int n1,
        const uint4* __restrict__ a2, int n2,
        float4* __restrict__ out) {
    __shared__ unsigned shh[HBINS];
    int mode = g_mode;
    int tid = blockIdx.x * blockDim.x + threadIdx.x;
    int stride = gridDim.x * blockDim.x;
    float* of = (float*)out;

    if (mode == 0) {
        for (int j = threadIdx.x; j < 256; j += NT) shh[j] = 0;
        __syncthreads();
        unsigned cc = g_cand_cnt;
        if (cc > CBUF_CAP) cc = CBUF_CAP;
        const unsigned pref24 = g_pref;
        for (unsigned i = tid; i < cc; i += (unsigned)stride) {
            unsigned k = g_ck[i];
            unsigned p24 = k >> 8;
            if (p24 < pref24) {
                of[g_ci[i]] = 0.0f;
            } else if (p24 == pref24) {
                unsigned pos = atomicAdd(&g_mcnt, 1u);
                if (pos < MCAP) { g_mk[pos] = k; g_mi[pos] = g_ci[i]; }
                atomicAdd(&shh[k & 255u], 1u);
            }
        }
        __syncthreads();
        for (int j = threadIdx.x; j < 256; j += NT)
            if (shh[j]) atomicAdd(&g_h[j], shh[j]);
        __threadfence();
        __shared__ unsigned islast;
        if (threadIdx.x == 0)
            islast = (atomicAdd(&g_ctr[2], 1u) == gridDim.x - 1u) ? 1u : 0u;
        __syncthreads();
        if (!islast) return;

        select_digitN(256, 8, 1);              // final: g_key32, g_thresh
        unsigned kf = g_key32;
        unsigned mc = g_mcnt;
        if (mc <= MCAP) {
            for (unsigned i = threadIdx.x; i < mc; i += NT)
                if (g_mk[i] < kf) of[g_mi[i]] = 0.0f;
        } else {
            for (unsigned i = threadIdx.x; i < cc; i += NT) {
                unsigned k = g_ck[i];
                if ((k >> 8) == pref24 && k < kf) of[g_ci[i]] = 0.0f;
            }
        }
        __syncthreads();
        if (threadIdx.x == 0) {
            g_cand_cnt = 0; g_mcnt = 0; g_ctr[1] = 0; g_ctr[2] = 0;
        }
        return;
    }

    if (mode == 1) {
        // ---- Fallback: 3 full-read hist phases (12+12+8 bits), spins ----
#define FB_HIST(SDP, DMASK, PREF_SH)                                          \
        {                                                                     \
            const unsigned pref = *(volatile unsigned*)&g_pref;               \
            for (int i = tid; i < n0; i += stride) {                          \
                uint4 v = __ldcs(&a0[i]);                                     \
                unsigned kk[4] = {fmap_u(v.x), fmap_u(v.y),                   \
                                  fmap_u(v.z), fmap_u(v.w)};                  \
                for (int q = 0; q < 4; q++)                                   \
                    if ((PREF_SH) < 0 || (kk[q] >> (PREF_SH)) == pref)        \
                        atomicAdd(&shh[(kk[q] >> (SDP)) & (DMASK)], 1u);      \
            }                                                                 \
            for (int i = tid; i < n1; i += stride) {                          \
                uint4 v = __ldcs(&a1[i]);                                     \
                unsigned kk[4] = {fmap_u(v.x), fmap_u(v.y),                   \
                                  fmap_u(v.z), fmap_u(v.w)};                  \
                for (int q = 0; q < 4; q++)                                   \
                    if ((PREF_SH) < 0 || (kk[q] >> (PREF_SH)) == pref)        \
                        atomicAdd(&shh[(kk[q] >> (SDP)) & (DMASK)], 1u);      \
            }                                                                 \
            for (int i = tid; i < n2; i += stride) {                          \
                uint4 v = __ldcs(&a2[i]);                                     \
                unsigned kk[4] = {fmap_u(v.x), fmap_u(v.y),                   \
                                  fmap_u(v.z), fmap_u(v.w)};                  \
                for (int q = 0; q < 4; q++)                                   \
                    if ((PREF_SH) < 0 || (kk[q] >> (PREF_SH)) == pref)        \
                        atomicAdd(&shh[(kk[q] >> (SDP)) & (DMASK)], 1u);      \
            }                                                                 \
        }
        for (int j = threadIdx.x; j < HBINS; j += NT) shh[j] = 0;
        __syncthreads();
        FB_HIST(20, 4095u, -1)
        __syncthreads();
        for (int j = threadIdx.x; j < HBINS; j += NT)
            if (shh[j]) atomicAdd(&g_h[j], shh[j]);
        fb_sync(3, 4096, 12, 0);

        for (int j = threadIdx.x; j < HBINS; j += NT) shh[j] = 0;
        __syncthreads();
        FB_HIST(8, 4095u, 20)
        __syncthreads();
        for (int j = threadIdx.x; j < HBINS; j += NT)
            if (shh[j]) atomicAdd(&g_h[j], shh[j]);
        fb_sync(4, 4096, 12, 0);

        for (int j = threadIdx.x; j < 256; j += NT) shh[j] = 0;
        __syncthreads();
        FB_HIST(0, 255u, 8)
        __syncthreads();
        for (int j = threadIdx.x; j < 256; j += NT)
            if (shh[j]) atomicAdd(&g_h[j], shh[j]);
        fb_sync(5, 256, 8, 1);
#undef FB_HIST
    }

    // ---- Full rewrite (mode 1 after select, or mode 2 with thresh=0) ----
    {
        const float th = *(volatile float*)&g_thresh;
        const float4* f0 = (const float4*)a0;
        const float4* f1 = (const float4*)a1;
        const float4* f2 = (const float4*)a2;
        for (int i = tid; i < n0; i += stride) {
            float4 v = f0[i];
            v.x = (v.x < th) ? 0.0f : v.x;  v.y = (v.y < th) ? 0.0f : v.y;
            v.z = (v.z < th) ? 0.0f : v.z;  v.w = (v.w < th) ? 0.0f : v.w;
            out[i] = v;
        }
        float4* o1 = out + n0;
        for (int i = tid; i < n1; i += stride) {
            float4 v = f1[i];
            v.x = (v.x < th) ? 0.0f : v.x;  v.y = (v.y < th) ? 0.0f : v.y;
            v.z = (v.z < th) ? 0.0f : v.z;  v.w = (v.w < th) ? 0.0f : v.w;
            o1[i] = v;
        }
        float4* o2 = out + n0 + n1;
        for (int i = tid; i < n2; i += stride) {
            float4 v = f2[i];
            v.x = (v.x < th) ? 0.0f : v.x;  v.y = (v.y < th) ? 0.0f : v.y;
            v.z = (v.z < th) ? 0.0f : v.z;  v.w = (v.w < th) ? 0.0f : v.w;
            o2[i] = v;
        }
    }
    __threadfence();
    __syncthreads();
    if (threadIdx.x == 0) {
        if (atomicAdd(&g_ctr[2], 1u) == gridDim.x - 1u) {
            g_ctr[1] = 0; g_ctr[2] = 0;
            g_cand_cnt = 0; g_mcnt = 0;
            g_ctr[3] = 0; g_ctr[4] = 0; g_ctr[5] = 0;
            g_go[3] = 0; g_go[4] = 0; g_go[5] = 0;
        }
    }
}

// ============================================================================
extern "C" void kernel_launch(void* const* d_in, const int* in_sizes, int n_in,
                              void* d_out, int out_size) {
    const float* e  = (const float*)d_in[0];
    const float* m  = (const float*)d_in[1];
    const float* dp = (const float*)d_in[2];
    const int* mf_ptr = (n_in >= 4) ? (const int*)d_in[3] : nullptr;
    int ne = in_sizes[0], nm = in_sizes[1], nd = in_sizes[2];
    long long ntot = (long long)ne + (long long)nm + (long long)nd;
    int ne4 = ne / 4, nm4 = nm / 4, nd4 = nd / 4;

    const uint4* u0 = (const uint4*)e;
    const uint4* u1 = (const uint4*)m;
    const uint4* u2 = (const uint4*)dp;

    k_pass1<<<NB, NT>>>(u0, ne4, u1, nm4, u2, nd4, (uint4*)d_out,
                        mf_ptr, 500000, ntot);
    k_round2<<<NB, NT>>>((float4*)d_out);
    k_tail<<<TGRID, NT>>>(u0, ne4, u1, nm4, u2, nd4, (float4*)d_out);
}

// round 16
// speedup vs baseline: 1.1202x; 1.1202x over previous
#include <cuda_runtime.h>
#include <stdint.h>

// ============================================================================
// One-sweep speculative radix-select threshold kernel
// (v16 = R14 + predicated round2 loads + tail grid 256).
//
// thresh = rank-mf (0-based) entry of the descending sort of all inputs.
// out[i] = x[i] < thresh ? 0 : x[i].
//
// Key map (order-preserving): key = u ^ (sign ? 0xFFFFFFFF : 0x80000000).
//
// THREE launches:
//  pass1:  read all, write out thresholded at 1.9375. Candidates allocated
//          into per-WARP slices via per-warp smem atomic counters, smem
//          4096-bin hist of key>>20. Last block decides mode + selects
//          digit1 (12 bits).
//  round2: warp-per-slice, register-resident keys (loads predicated on
//          slice count), warp-scan + one global atomic per block dense
//          compaction, smem hist bits[19:8]. Last block selects digit2.
//  tail:   scan dense buffer; zero below 24-bit prefix; collect matched
//          stragglers + 256-bin hist of bits[7:0]; last block selects final
//          digit -> exact key, zeroes stragglers below it.
//          Fallback (mode 1): full-read hist phases + rewrite, gated.
//          Trivial (mode 2): thresh=0 rewrite.
// ============================================================================

#define NB     1024
#define NT     256
#define NWARP  (NB * NT / 32)     // 8192
#define SLICE  256u
#define CBUF_CAP (NWARP * SLICE)  // 2M entries
#define MCAP   16384u
#define FTH    1.9375f
#define HBINS  4096
#define TGRID  256

__device__ unsigned g_h[HBINS];
__device__ unsigned g_key[NWARP * SLICE];   // 8 MB
__device__ unsigned g_idx[NWARP * SLICE];   // 8 MB
__device__ unsigned g_ck[CBUF_CAP];         // 8 MB dense in-bin keys
__device__ unsigned g_ci[CBUF_CAP];         // 8 MB dense in-bin idx
__device__ unsigned g_mk[MCAP];             // straggler keys
__device__ unsigned g_mi[MCAP];             // straggler idx
__device__ unsigned g_warpcnt[NWARP];
__device__ unsigned g_ctr[8];
__device__ unsigned g_go[8];
__device__ unsigned g_cand_cnt;
__device__ unsigned g_mcnt;
__device__ unsigned g_nscratch;
__device__ int      g_mode;       // 0=spec, 1=fallback, 2=trivial
__device__ int      g_overflow;
__device__ unsigned g_pref;       // accumulated digit prefix (right-aligned)
__device__ unsigned g_rank;       // residual rank
__device__ unsigned g_key32;      // final exact key
__device__ float    g_thresh;

__device__ __forceinline__ unsigned fmap_u(unsigned u) {
    return u ^ ((unsigned)((int)u >> 31) | 0x80000000u);
}
__device__ __forceinline__ float finv_map(unsigned k) {
    unsigned u = (k & 0x80000000u) ? (k ^ 0x80000000u) : ~k;
    return __uint_as_float(u);
}

// Block-cooperative descending rank-select over g_h[0..nbins). 256 threads.
__device__ void select_digitN(int nbins, int append_bits, int final_stage) {
    __shared__ unsigned tsum[256];
    __shared__ unsigned wsum[8];
    int per = nbins >> 8;
    unsigned s = 0;
    int base = threadIdx.x * per;
    for (int j = 0; j < per; j++) s += g_h[base + j];
    tsum[threadIdx.x] = s;
    unsigned ws = s;
    ws += __shfl_xor_sync(0xFFFFFFFFu, ws, 16);
    ws += __shfl_xor_sync(0xFFFFFFFFu, ws, 8);
    ws += __shfl_xor_sync(0xFFFFFFFFu, ws, 4);
    ws += __shfl_xor_sync(0xFFFFFFFFu, ws, 2);
    ws += __shfl_xor_sync(0xFFFFFFFFu, ws, 1);
    if ((threadIdx.x & 31) == 0) wsum[threadIdx.x >> 5] = ws;
    __syncthreads();
    if (threadIdx.x == 0) {
        unsigned r = g_rank;
        int w = 7;
        for (; w > 0; w--) { if (r < wsum[w]) break; r -= wsum[w]; }
        int t = 31;
        for (; t > 0; t--) { unsigned c = tsum[w * 32 + t]; if (r < c) break; r -= c; }
        int b = (w * 32 + t) * per;
        int j = per - 1;
        for (; j > 0; j--) { unsigned c = g_h[b + j]; if (r < c) break; r -= c; }
        unsigned d = (unsigned)(b + j);
        unsigned p = (g_pref << append_bits) | d;
        g_pref = p;
        g_rank = r;
        if (final_stage) { g_key32 = p; g_thresh = finv_map(p); }
    }
    __syncthreads();
    for (int j = threadIdx.x; j < nbins; j += 256) g_h[j] = 0;
    __syncthreads();
}

// Spin barrier used ONLY by the fallback path (mode 1).
__device__ void fb_sync(int ph, int nbins, int append_bits, int fin) {
    __threadfence();
    __syncthreads();
    __shared__ unsigned slast;
    if (threadIdx.x == 0)
        slast = (atomicAdd(&g_ctr[ph], 1u) == gridDim.x - 1u) ? 1u : 0u;
    __syncthreads();
    if (slast) {
        select_digitN(nbins, append_bits, fin);
        __threadfence();
        if (threadIdx.x == 0) *(volatile unsigned*)&g_go[ph] = 1u;
    } else {
        if (threadIdx.x == 0)
            while (*(volatile unsigned*)&g_go[ph] == 0u) __nanosleep(64);
        __syncthreads();
        __threadfence();
    }
    __syncthreads();
}

// ---------------------------------------------------------------------------
__global__ void __launch_bounds__(NT) k_pass1(
        const uint4* __restrict__ a0, int n0,
        const uint4* __restrict__ a1, int n1,
        const uint4* __restrict__ a2, int n2,
        uint4* __restrict__ out,
        const int* mf_ptr, int host_mf, long long ntot) {
    __shared__ unsigned shh[HBINS];
    __shared__ unsigned swo[NT / 32];     // per-warp slice write cursors
    for (int j = threadIdx.x; j < HBINS; j += NT) shh[j] = 0;
    if (threadIdx.x < NT / 32) swo[threadIdx.x] = 0;
    __syncthreads();

    int tid = blockIdx.x * blockDim.x + threadIdx.x;
    int stride = gridDim.x * blockDim.x;
    unsigned wip = threadIdx.x >> 5;
    unsigned gw = (unsigned)tid >> 5;
    unsigned sbase = gw * SLICE;
    bool ovf = false;

#define P1_EMIT(KU, IB, P)                                                    \
    do {                                                                      \
        unsigned kk = fmap_u(KU);                                             \
        g_key[P] = kk; g_idx[P] = (IB);                                       \
        atomicAdd(&shh[kk >> 20], 1u);                                        \
        (P)++;                                                                \
    } while (0)

#define P1_BODY(ARR, N, OUTP, EO)                                             \
    for (int i = tid; i < (N); i += stride) {                                 \
        uint4 v = __ldcs(&(ARR)[i]);                                          \
        bool c0 = !(__uint_as_float(v.x) < FTH);                              \
        bool c1 = !(__uint_as_float(v.y) < FTH);                              \
        bool c2 = !(__uint_as_float(v.z) < FTH);                              \
        bool c3 = !(__uint_as_float(v.w) < FTH);                              \
        uint4 w;                                                              \
        w.x = c0 ? v.x : 0u;  w.y = c1 ? v.y : 0u;                            \
        w.z = c2 ? v.z : 0u;  w.w = c3 ? v.w : 0u;                            \
        __stcs(&(OUTP)[i], w);                                                \
        unsigned cnt = (unsigned)c0 + (unsigned)c1 +                          \
                       (unsigned)c2 + (unsigned)c3;                           \
        if (cnt) {                                                            \
            unsigned off = atomicAdd(&swo[wip], cnt);                         \
            if (off + cnt <= SLICE) {                                         \
                unsigned p = sbase + off;                                     \
                unsigned ib = (EO) + 4u * (unsigned)i;                        \
                if (c0) P1_EMIT(v.x, ib, p);                                  \
                if (c1) P1_EMIT(v.y, ib + 1u, p);                             \
                if (c2) P1_EMIT(v.z, ib + 2u, p);                             \
                if (c3) P1_EMIT(v.w, ib + 3u, p);                             \
            } else {                                                          \
                ovf = true;                                                   \
            }                                                                 \
        }                                                                     \
    }
    P1_BODY(a0, n0, out, 0u)
    P1_BODY(a1, n1, out + n0, 4u * (unsigned)n0)
    P1_BODY(a2, n2, out + n0 + n1, 4u * (unsigned)(n0 + n1))
#undef P1_BODY
#undef P1_EMIT

    if (ovf) g_overflow = 1;
    __syncthreads();
    if ((threadIdx.x & 31u) == 0) {
        unsigned wo = swo[wip];
        g_warpcnt[gw] = (wo > SLICE) ? SLICE : wo;
        atomicAdd(&g_nscratch, wo);
    }
    for (int j = threadIdx.x; j < HBINS; j += NT)
        if (shh[j]) atomicAdd(&g_h[j], shh[j]);
    __threadfence();

    __shared__ unsigned islast;
    if (threadIdx.x == 0)
        islast = (atomicAdd(&g_ctr[0], 1u) == gridDim.x - 1u) ? 1u : 0u;
    __syncthreads();
    if (!islast) return;

    __shared__ int smode;
    if (threadIdx.x == 0) {
        long long mf = (mf_ptr != nullptr) ? (long long)(*mf_ptr)
                                           : (long long)host_mf;
        if (mf < 0) mf = 0;
        int mode;
        if (mf >= ntot)                                        mode = 2;
        else if (g_overflow || (long long)g_nscratch < mf + 1) mode = 1;
        else                                                   mode = 0;
        g_mode = mode;
        smode = mode;
        g_rank = (unsigned)mf;
        g_pref = 0;
        if (mode == 2) g_thresh = 0.0f;
    }
    __syncthreads();
    if (smode == 0) {
        select_digitN(HBINS, 12, 0);
    } else {
        for (int j = threadIdx.x; j < HBINS; j += NT) g_h[j] = 0;
    }
}

// ---------------------------------------------------------------------------
// round2: warp w handles slice w. Single pass, register-resident keys
// (uint4 loads predicated on slice count), one global atomic per block.
__global__ void __launch_bounds__(NT) k_round2(float4* __restrict__ out) {
    __shared__ unsigned shh[HBINS];
    __shared__ unsigned wcnt_s[NT / 32];
    __shared__ unsigned wbase_s[NT / 32];
    int mode = g_mode;
    if (mode == 0) {
        for (int j = threadIdx.x; j < HBINS; j += NT) shh[j] = 0;
        __syncthreads();

        unsigned lane = threadIdx.x & 31u;
        unsigned wip = threadIdx.x >> 5;
        unsigned w = (blockIdx.x * blockDim.x + threadIdx.x) >> 5;
        const unsigned pref12 = g_pref;
        float* of = (float*)out;

        unsigned cnt = g_warpcnt[w];
        if (cnt > SLICE) cnt = SLICE;
        const uint4* kp4 = (const uint4*)&g_key[w * SLICE];
        const unsigned* ip = &g_idx[w * SLICE];

        uint4 z = make_uint4(0u, 0u, 0u, 0u);
        uint4 ka = (4u * lane < cnt)          ? kp4[lane]      : z;
        uint4 kb = (128u + 4u * lane < cnt)   ? kp4[lane + 32] : z;
        unsigned keys[8] = {ka.x, ka.y, ka.z, ka.w, kb.x, kb.y, kb.z, kb.w};

        unsigned mc = 0, mmask = 0;
#pragma unroll
        for (int r = 0; r < 8; r++) {
            unsigned e = (r < 4) ? (4u * lane + (unsigned)r)
                                 : (128u + 4u * lane + (unsigned)(r - 4));
            bool valid = e < cnt;
            unsigned p12 = keys[r] >> 20;
            if (valid && p12 < pref12) of[ip[e]] = 0.0f;
            if (valid && p12 == pref12) { mc++; mmask |= 1u << r; }
        }

        unsigned incl = mc;
#pragma unroll
        for (int o = 1; o < 32; o <<= 1) {
            unsigned t = __shfl_up_sync(0xFFFFFFFFu, incl, o);
            if (lane >= (unsigned)o) incl += t;
        }
        unsigned wtot = __shfl_sync(0xFFFFFFFFu, incl, 31);
        unsigned texcl = incl - mc;
        if (lane == 0) wcnt_s[wip] = wtot;
        __syncthreads();
        if (threadIdx.x == 0) {
            unsigned tot = 0, b[NT / 32];
            for (int q = 0; q < NT / 32; q++) { b[q] = tot; tot += wcnt_s[q]; }
            unsigned base = tot ? atomicAdd(&g_cand_cnt, tot) : 0u;
            for (int q = 0; q < NT / 32; q++) wbase_s[q] = base + b[q];
        }
        __syncthreads();
        unsigned pos = wbase_s[wip] + texcl;

#pragma unroll
        for (int r = 0; r < 8; r++) {
            if ((mmask >> r) & 1u) {
                unsigned e = (r < 4) ? (4u * lane + (unsigned)r)
                                     : (128u + 4u * lane + (unsigned)(r - 4));
                if (pos < CBUF_CAP) {
                    g_ck[pos] = keys[r];
                    g_ci[pos] = ip[e];
                }
                atomicAdd(&shh[(keys[r] >> 8) & 4095u], 1u);
                pos++;
            }
        }
        __syncthreads();
        for (int j = threadIdx.x; j < HBINS; j += NT)
            if (shh[j]) atomicAdd(&g_h[j], shh[j]);
    }
    __threadfence();
    __shared__ unsigned islast;
    if (threadIdx.x == 0)
        islast = (atomicAdd(&g_ctr[1], 1u) == gridDim.x - 1u) ? 1u : 0u;
    __syncthreads();
    if (!islast) return;

    if (threadIdx.x == 0) {
        g_ctr[0] = 0; g_nscratch = 0; g_overflow = 0;
    }
    if (mode == 0) select_digitN(HBINS, 12, 0);   // -> 24-bit prefix
}

// ---------------------------------------------------------------------------
__global__ void __launch_bounds__(NT) k_tail(
        const uint4* __restrict__ a0, int n0,
        const uint4* __restrict__ a1, int n1,
        const uint4* __restrict__ a2, int n2,
        float4* __restrict__ out) {
    __shared__ unsigned shh[HBINS];
    int mode = g_mode;
    int tid = blockIdx.x * blockDim.x + threadIdx.x;
    int stride = gridDim.x * blockDim.x;
    float* of = (float*)out;

    if (mode == 0) {
        for (int j = threadIdx.x; j < 256; j += NT) shh[j] = 0;
        __syncthreads();
        unsigned cc = g_cand_cnt;
        if (cc > CBUF_CAP) cc = CBUF_CAP;
        const unsigned pref24 = g_pref;
        for (unsigned i = tid; i < cc; i += (unsigned)stride) {
            unsigned k = g_ck[i];
            unsigned p24 = k >> 8;
            if (p24 < pref24) {
                of[g_ci[i]] = 0.0f;
            } else if (p24 == pref24) {
                unsigned pos = atomicAdd(&g_mcnt, 1u);
                if (pos < MCAP) { g_mk[pos] = k; g_mi[pos] = g_ci[i]; }
                atomicAdd(&shh[k & 255u], 1u);
            }
        }
        __syncthreads();
        for (int j = threadIdx.x; j < 256; j += NT)
            if (shh[j]) atomicAdd(&g_h[j], shh[j]);
        __threadfence();
        __shared__ unsigned islast;
        if (threadIdx.x == 0)
            islast = (atomicAdd(&g_ctr[2], 1u) == gridDim.x - 1u) ? 1u : 0u;
        __syncthreads();
        if (!islast) return;

        select_digitN(256, 8, 1);              // final: g_key32, g_thresh
        unsigned kf = g_key32;
        unsigned mc = g_mcnt;
        if (mc <= MCAP) {
            for (unsigned i = threadIdx.x; i < mc; i += NT)
                if (g_mk[i] < kf) of[g_mi[i]] = 0.0f;
        } else {
            for (unsigned i = threadIdx.x; i < cc; i += NT) {
                unsigned k = g_ck[i];
                if ((k >> 8) == pref24 && k < kf) of[g_ci[i]] = 0.0f;
            }
        }
        __syncthreads();
        if (threadIdx.x == 0) {
            g_cand_cnt = 0; g_mcnt = 0; g_ctr[1] = 0; g_ctr[2] = 0;
        }
        return;
    }

    if (mode == 1) {
        // ---- Fallback: 3 full-read hist phases (12+12+8 bits), spins ----
#define FB_HIST(SDP, DMASK, PREF_SH)                                          \
        {                                                                     \
            const unsigned pref = *(volatile unsigned*)&g_pref;               \
            for (int i = tid; i < n0; i += stride) {                          \
                uint4 v = __ldcs(&a0[i]);                                     \
                unsigned kk[4] = {fmap_u(v.x), fmap_u(v.y),                   \
                                  fmap_u(v.z), fmap_u(v.w)};                  \
                for (int q = 0; q < 4; q++)                                   \
                    if ((PREF_SH) < 0 || (kk[q] >> (PREF_SH)) == pref)        \
                        atomicAdd(&shh[(kk[q] >> (SDP)) & (DMASK)], 1u);      \
            }                                                                 \
            for (int i = tid; i < n1; i += stride) {                          \
                uint4 v = __ldcs(&a1[i]);                                     \
                unsigned kk[4] = {fmap_u(v.x), fmap_u(v.y),                   \
                                  fmap_u(v.z), fmap_u(v.w)};                  \
                for (int q = 0; q < 4; q++)                                   \
                    if ((PREF_SH) < 0 || (kk[q] >> (PREF_SH)) == pref)        \
                        atomicAdd(&shh[(kk[q] >> (SDP)) & (DMASK)], 1u);      \
            }                                                                 \
            for (int i = tid; i < n2; i += stride) {                          \
                uint4 v = __ldcs(&a2[i]);                                     \
                unsigned kk[4] = {fmap_u(v.x), fmap_u(v.y),                   \
                                  fmap_u(v.z), fmap_u(v.w)};                  \
                for (int q = 0; q < 4; q++)                                   \
                    if ((PREF_SH) < 0 || (kk[q] >> (PREF_SH)) == pref)        \
                        atomicAdd(&shh[(kk[q] >> (SDP)) & (DMASK)], 1u);      \
            }                                                                 \
        }
        for (int j = threadIdx.x; j < HBINS; j += NT) shh[j] = 0;
        __syncthreads();
        FB_HIST(20, 4095u, -1)
        __syncthreads();
        for (int j = threadIdx.x; j < HBINS; j += NT)
            if (shh[j]) atomicAdd(&g_h[j], shh[j]);
        fb_sync(3, 4096, 12, 0);

        for (int j = threadIdx.x; j < HBINS; j += NT) shh[j] = 0;
        __syncthreads();
        FB_HIST(8, 4095u, 20)
        __syncthreads();
        for (int j = threadIdx.x; j < HBINS; j += NT)
            if (shh[j]) atomicAdd(&g_h[j], shh[j]);
        fb_sync(4, 4096, 12, 0);

        for (int j = threadIdx.x; j < 256; j += NT) shh[j] = 0;
        __syncthreads();
        FB_HIST(0, 255u, 8)
        __syncthreads();
        for (int j = threadIdx.x; j < 256; j += NT)
            if (shh[j]) atomicAdd(&g_h[j], shh[j]);
        fb_sync(5, 256, 8, 1);
#undef FB_HIST
    }

    // ---- Full rewrite (mode 1 after select, or mode 2 with thresh=0) ----
    {
        const float th = *(volatile float*)&g_thresh;
        const float4* f0 = (const float4*)a0;
        const float4* f1 = (const float4*)a1;
        const float4* f2 = (const float4*)a2;
        for (int i = tid; i < n0; i += stride) {
            float4 v = f0[i];
            v.x = (v.x < th) ? 0.0f : v.x;  v.y = (v.y < th) ? 0.0f : v.y;
            v.z = (v.z < th) ? 0.0f : v.z;  v.w = (v.w < th) ? 0.0f : v.w;
            out[i] = v;
        }
        float4* o1 = out + n0;
        for (int i = tid; i < n1; i += stride) {
            float4 v = f1[i];
            v.x = (v.x < th) ? 0.0f : v.x;  v.y = (v.y < th) ? 0.0f : v.y;
            v.z = (v.z < th) ? 0.0f : v.z;  v.w = (v.w < th) ? 0.0f : v.w;
            o1[i] = v;
        }
        float4* o2 = out + n0 + n1;
        for (int i = tid; i < n2; i += stride) {
            float4 v = f2[i];
            v.x = (v.x < th) ? 0.0f : v.x;  v.y = (v.y < th) ? 0.0f : v.y;
            v.z = (v.z < th) ? 0.0f : v.z;  v.w = (v.w < th) ? 0.0f : v.w;
            o2[i] = v;
        }
    }
    __threadfence();
    __syncthreads();
    if (threadIdx.x == 0) {
        if (atomicAdd(&g_ctr[2], 1u) == gridDim.x - 1u) {
            g_ctr[1] = 0; g_ctr[2] = 0;
            g_cand_cnt = 0; g_mcnt = 0;
            g_ctr[3] = 0; g_ctr[4] = 0; g_ctr[5] = 0;
            g_go[3] = 0; g_go[4] = 0; g_go[5] = 0;
        }
    }
}

// ============================================================================
extern "C" void kernel_launch(void* const* d_in, const int* in_sizes, int n_in,
                              void* d_out, int out_size) {
    const float* e  = (const float*)d_in[0];
    const float* m  = (const float*)d_in[1];
    const float* dp = (const float*)d_in[2];
    const int* mf_ptr = (n_in >= 4) ? (const int*)d_in[3] : nullptr;
    int ne = in_sizes[0], nm = in_sizes[1], nd = in_sizes[2];
    long long ntot = (long long)ne + (long long)nm + (long long)nd;
    int ne4 = ne / 4, nm4 = nm / 4, nd4 = nd / 4;

    const uint4* u0 = (const uint4*)e;
    const uint4* u1 = (const uint4*)m;
    const uint4* u2 = (const uint4*)dp;

    k_pass1<<<NB, NT>>>(u0, ne4, u1, nm4, u2, nd4, (uint4*)d_out,
                        mf_ptr, 500000, ntot);
    k_round2<<<NB, NT>>>((float4*)d_out);
    k_tail<<<TGRID, NT>>>(u0, ne4, u1, nm4, u2, nd4, (float4*)d_out);
}

// round 17
// speedup vs baseline: 1.2932x; 1.1544x over previous
#include <cuda_runtime.h>
#include <stdint.h>

// ============================================================================
// One-sweep speculative radix-select threshold kernel (v17 = R16 with a
// range-binned first digit; TWO launches, no tail kernel).
//
// thresh = rank-mf (0-based) entry of the descending sort of all inputs.
// out[i] = x[i] < thresh ? 0 : x[i].
//
// Key map (order-preserving): key = u ^ (sign ? 0xFFFFFFFF : 0x80000000).
//
//  pass1:  read all, write out thresholded at 1.9375. Candidates allocated
//          into per-WARP slices via per-warp smem atomic counters; smem
//          4096-bin RANGE hist: bin = min((key-FKEY)>>12, 4095). Last block
//          decides mode + selects the bin (exact in-bin count known; count
//          > MCAP or bin==4095 -> fallback).
//  round2: warp-per-slice register-resident scan; zero out[] for bins below
//          the selected one; collect in-bin entries (block-aggregated alloc,
//          <= MCAP guaranteed) into g_mk/g_mi. Last-arriving block: one
//          4096-bin smem hist of (k-FKEY)&4095 over collected entries ->
//          exact key; zero collected entries below it; reset replay state.
//          Fallback (mode 1): full-read hist phases + rewrite (spin
//          barriers; grid fully resident). Trivial (mode 2): rewrite.
// ============================================================================

#define NB     1024
#define NT     256
#define NWARP  (NB * NT / 32)     // 8192
#define SLICE  256u
#define MCAP   16384u
#define FTH    1.9375f
#define FKEY   0xBFF80000u        // key(+1.9375f)
#define HBINS  4096

__device__ unsigned g_h[HBINS];
__device__ unsigned g_key[NWARP * SLICE];   // 8 MB
__device__ unsigned g_idx[NWARP * SLICE];   // 8 MB
__device__ unsigned g_mk[MCAP];             // in-bin keys (64 KB)
__device__ unsigned g_mi[MCAP];             // in-bin idx  (64 KB)
__device__ unsigned g_warpcnt[NWARP];
__device__ unsigned g_ctr[8];
__device__ unsigned g_go[8];
__device__ unsigned g_mcnt;
__device__ unsigned g_nscratch;
__device__ int      g_mode;       // 0=spec, 1=fallback, 2=trivial
__device__ int      g_overflow;
__device__ unsigned g_pref;       // spec: selected bin; fb: digit prefix
__device__ unsigned g_rank;       // residual rank
__device__ unsigned g_key32;      // final exact key
__device__ float    g_thresh;

__device__ __forceinline__ unsigned fmap_u(unsigned u) {
    return u ^ ((unsigned)((int)u >> 31) | 0x80000000u);
}
__device__ __forceinline__ float finv_map(unsigned k) {
    unsigned u = (k & 0x80000000u) ? (k ^ 0x80000000u) : ~k;
    return __uint_as_float(u);
}
__device__ __forceinline__ unsigned range_bin(unsigned k) {
    unsigned d = (k - FKEY) >> 12;
    return d > 4095u ? 4095u : d;
}

// Block-cooperative descending rank-select over h[0..nbins) (nbins multiple
// of 256). Call with 256 threads. Returns bin + residual rank to ALL threads.
__device__ void block_select(const unsigned* h, int nbins, unsigned r_in,
                             unsigned* out_bin, unsigned* out_r) {
    __shared__ unsigned tsum[256];
    __shared__ unsigned wsum[8];
    __shared__ unsigned res2[2];
    int per = nbins >> 8;
    unsigned s = 0;
    int base = threadIdx.x * per;
    for (int j = 0; j < per; j++) s += h[base + j];
    tsum[threadIdx.x] = s;
    unsigned ws = s;
    ws += __shfl_xor_sync(0xFFFFFFFFu, ws, 16);
    ws += __shfl_xor_sync(0xFFFFFFFFu, ws, 8);
    ws += __shfl_xor_sync(0xFFFFFFFFu, ws, 4);
    ws += __shfl_xor_sync(0xFFFFFFFFu, ws, 2);
    ws += __shfl_xor_sync(0xFFFFFFFFu, ws, 1);
    if ((threadIdx.x & 31) == 0) wsum[threadIdx.x >> 5] = ws;
    __syncthreads();
    if (threadIdx.x == 0) {
        unsigned r = r_in;
        int w = 7;
        for (; w > 0; w--) { if (r < wsum[w]) break; r -= wsum[w]; }
        int t = 31;
        for (; t > 0; t--) { unsigned c = tsum[w * 32 + t]; if (r < c) break; r -= c; }
        int b = (w * 32 + t) * per;
        int j = per - 1;
        for (; j > 0; j--) { unsigned c = h[b + j]; if (r < c) break; r -= c; }
        res2[0] = (unsigned)(b + j);
        res2[1] = r;
    }
    __syncthreads();
    *out_bin = res2[0];
    *out_r = res2[1];
    __syncthreads();
}

// Fallback digit select over g_h (updates g_pref/g_rank, zeroes g_h).
__device__ void select_digitN(int nbins, int append_bits, int final_stage) {
    unsigned b, r;
    block_select(g_h, nbins, g_rank, &b, &r);
    if (threadIdx.x == 0) {
        unsigned p = (g_pref << append_bits) | b;
        g_pref = p;
        g_rank = r;
        if (final_stage) { g_key32 = p; g_thresh = finv_map(p); }
    }
    __syncthreads();
    for (int j = threadIdx.x; j < nbins; j += 256) g_h[j] = 0;
    __syncthreads();
}

// Spin barrier used ONLY by the fallback path (grid fully resident).
__device__ void fb_sync(int ph, int nbins, int append_bits, int fin) {
    __threadfence();
    __syncthreads();
    __shared__ unsigned slast;
    if (threadIdx.x == 0)
        slast = (atomicAdd(&g_ctr[ph], 1u) == gridDim.x - 1u) ? 1u : 0u;
    __syncthreads();
    if (slast) {
        select_digitN(nbins, append_bits, fin);
        __threadfence();
        if (threadIdx.x == 0) *(volatile unsigned*)&g_go[ph] = 1u;
    } else {
        if (threadIdx.x == 0)
            while (*(volatile unsigned*)&g_go[ph] == 0u) __nanosleep(64);
        __syncthreads();
        __threadfence();
    }
    __syncthreads();
}

// ---------------------------------------------------------------------------
__global__ void __launch_bounds__(NT) k_pass1(
        const uint4* __restrict__ a0, int n0,
        const uint4* __restrict__ a1, int n1,
        const uint4* __restrict__ a2, int n2,
        uint4* __restrict__ out,
        const int* mf_ptr, int host_mf, long long ntot) {
    __shared__ unsigned shh[HBINS];
    __shared__ unsigned swo[NT / 32];     // per-warp slice write cursors
    for (int j = threadIdx.x; j < HBINS; j += NT) shh[j] = 0;
    if (threadIdx.x < NT / 32) swo[threadIdx.x] = 0;
    __syncthreads();

    int tid = blockIdx.x * blockDim.x + threadIdx.x;
    int stride = gridDim.x * blockDim.x;
    unsigned wip = threadIdx.x >> 5;
    unsigned gw = (unsigned)tid >> 5;
    unsigned sbase = gw * SLICE;
    bool ovf = false;

#define P1_EMIT(KU, IB, P)                                                    \
    do {                                                                      \
        unsigned kk = fmap_u(KU);                                             \
        g_key[P] = kk; g_idx[P] = (IB);                                       \
        atomicAdd(&shh[range_bin(kk)], 1u);                                   \
        (P)++;                                                                \
    } while (0)

#define P1_BODY(ARR, N, OUTP, EO)                                             \
    for (int i = tid; i < (N); i += stride) {                                 \
        uint4 v = __ldcs(&(ARR)[i]);                                          \
        bool c0 = !(__uint_as_float(v.x) < FTH);                              \
        bool c1 = !(__uint_as_float(v.y) < FTH);                              \
        bool c2 = !(__uint_as_float(v.z) < FTH);                              \
        bool c3 = !(__uint_as_float(v.w) < FTH);                              \
        uint4 w;                                                              \
        w.x = c0 ? v.x : 0u;  w.y = c1 ? v.y : 0u;                            \
        w.z = c2 ? v.z : 0u;  w.w = c3 ? v.w : 0u;                            \
        __stcs(&(OUTP)[i], w);                                                \
        unsigned cnt = (unsigned)c0 + (unsigned)c1 +                          \
                       (unsigned)c2 + (unsigned)c3;                           \
        if (cnt) {                                                            \
            unsigned off = atomicAdd(&swo[wip], cnt);                         \
            if (off + cnt <= SLICE) {                                         \
                unsigned p = sbase + off;                                     \
                unsigned ib = (EO) + 4u * (unsigned)i;                        \
                if (c0) P1_EMIT(v.x, ib, p);                                  \
                if (c1) P1_EMIT(v.y, ib + 1u, p);                             \
                if (c2) P1_EMIT(v.z, ib + 2u, p);                             \
                if (c3) P1_EMIT(v.w, ib + 3u, p);                             \
            } else {                                                          \
                ovf = true;                                                   \
            }                                                                 \
        }                                                                     \
    }
    P1_BODY(a0, n0, out, 0u)
    P1_BODY(a1, n1, out + n0, 4u * (unsigned)n0)
    P1_BODY(a2, n2, out + n0 + n1, 4u * (unsigned)(n0 + n1))
#undef P1_BODY
#undef P1_EMIT

    if (ovf) g_overflow = 1;
    __syncthreads();
    if ((threadIdx.x & 31u) == 0) {
        unsigned wo = swo[wip];
        g_warpcnt[gw] = (wo > SLICE) ? SLICE : wo;
        atomicAdd(&g_nscratch, wo);
    }
    for (int j = threadIdx.x; j < HBINS; j += NT)
        if (shh[j]) atomicAdd(&g_h[j], shh[j]);
    __threadfence();

    __shared__ unsigned islast;
    if (threadIdx.x == 0)
        islast = (atomicAdd(&g_ctr[0], 1u) == gridDim.x - 1u) ? 1u : 0u;
    __syncthreads();
    if (!islast) return;

    __shared__ int smode;
    __shared__ unsigned srank;
    if (threadIdx.x == 0) {
        long long mf = (mf_ptr != nullptr) ? (long long)(*mf_ptr)
                                           : (long long)host_mf;
        if (mf < 0) mf = 0;
        int mode;
        if (mf >= ntot)                                        mode = 2;
        else if (g_overflow || (long long)g_nscratch < mf + 1) mode = 1;
        else                                                   mode = 0;
        g_mode = mode;
        smode = mode;
        srank = (unsigned)mf;
        g_rank = (unsigned)mf;
        g_pref = 0;
        if (mode == 2) g_thresh = 0.0f;
    }
    __syncthreads();
    if (smode == 0) {
        unsigned bin, r;
        block_select(g_h, HBINS, srank, &bin, &r);
        unsigned cnt_bin = g_h[bin];          // exact in-bin count
        if (threadIdx.x == 0) {
            if (bin >= 4095u || cnt_bin > MCAP) {
                g_mode = 1;                   // clamped bin / too fat
            } else {
                g_pref = bin; g_rank = r;
            }
        }
        __syncthreads();
    }
    for (int j = threadIdx.x; j < HBINS; j += NT) g_h[j] = 0;
}

// ---------------------------------------------------------------------------
// round2: warp w handles slice w; last-arriving block finishes everything.
__global__ void __launch_bounds__(NT) k_round2(
        const uint4* __restrict__ a0, int n0,
        const uint4* __restrict__ a1, int n1,
        const uint4* __restrict__ a2, int n2,
        float4* __restrict__ out) {
    __shared__ unsigned shh[HBINS];
    __shared__ unsigned wcnt_s[NT / 32];
    __shared__ unsigned wbase_s[NT / 32];
    int mode = g_mode;
    int tid = blockIdx.x * blockDim.x + threadIdx.x;
    int stride = gridDim.x * blockDim.x;
    unsigned lane = threadIdx.x & 31u;
    unsigned wip = threadIdx.x >> 5;
    float* of = (float*)out;

    if (mode == 0) {
        unsigned w = (unsigned)tid >> 5;
        const unsigned binsel = g_pref;

        unsigned cnt = g_warpcnt[w];
        if (cnt > SLICE) cnt = SLICE;
        const uint4* kp4 = (const uint4*)&g_key[w * SLICE];
        const unsigned* ip = &g_idx[w * SLICE];

        uint4 z = make_uint4(0u, 0u, 0u, 0u);
        uint4 ka = (4u * lane < cnt)        ? kp4[lane]      : z;
        uint4 kb = (128u + 4u * lane < cnt) ? kp4[lane + 32] : z;
        unsigned keys[8] = {ka.x, ka.y, ka.z, ka.w, kb.x, kb.y, kb.z, kb.w};

        unsigned mc = 0, mmask = 0;
#pragma unroll
        for (int r = 0; r < 8; r++) {
            unsigned e = (r < 4) ? (4u * lane + (unsigned)r)
                                 : (128u + 4u * lane + (unsigned)(r - 4));
            bool valid = e < cnt;
            unsigned d = range_bin(keys[r]);
            if (valid && d < binsel) of[ip[e]] = 0.0f;
            if (valid && d == binsel) { mc++; mmask |= 1u << r; }
        }

        unsigned incl = mc;
#pragma unroll
        for (int o = 1; o < 32; o <<= 1) {
            unsigned t = __shfl_up_sync(0xFFFFFFFFu, incl, o);
            if (lane >= (unsigned)o) incl += t;
        }
        unsigned wtot = __shfl_sync(0xFFFFFFFFu, incl, 31);
        unsigned texcl = incl - mc;
        if (lane == 0) wcnt_s[wip] = wtot;
        __syncthreads();
        if (threadIdx.x == 0) {
            unsigned tot = 0, b[NT / 32];
            for (int q = 0; q < NT / 32; q++) { b[q] = tot; tot += wcnt_s[q]; }
            unsigned base = tot ? atomicAdd(&g_mcnt, tot) : 0u;
            for (int q = 0; q < NT / 32; q++) wbase_s[q] = base + b[q];
        }
        __syncthreads();
        unsigned pos = wbase_s[wip] + texcl;

#pragma unroll
        for (int r = 0; r < 8; r++) {
            if ((mmask >> r) & 1u) {
                unsigned e = (r < 4) ? (4u * lane + (unsigned)r)
                                     : (128u + 4u * lane + (unsigned)(r - 4));
                if (pos < MCAP) { g_mk[pos] = keys[r]; g_mi[pos] = ip[e]; }
                pos++;
            }
        }
        __threadfence();
        __syncthreads();
        __shared__ unsigned slast;
        if (threadIdx.x == 0)
            slast = (atomicAdd(&g_ctr[1], 1u) == gridDim.x - 1u) ? 1u : 0u;
        __syncthreads();
        if (!slast) return;

        // ---- Finishing block: exact select within the bin ----
        unsigned m = *(volatile unsigned*)&g_mcnt;
        if (m > MCAP) m = MCAP;   // guaranteed <= MCAP; defensive
        for (int j = threadIdx.x; j < HBINS; j += NT) shh[j] = 0;
        __syncthreads();
        for (unsigned i = threadIdx.x; i < m; i += NT)
            atomicAdd(&shh[(g_mk[i] - FKEY) & 4095u], 1u);
        __syncthreads();
        unsigned d, rr;
        block_select(shh, 4096, g_rank, &d, &rr);
        unsigned kf = FKEY + (binsel << 12) + d;
        if (threadIdx.x == 0) { g_key32 = kf; g_thresh = finv_map(kf); }

        for (unsigned i = threadIdx.x; i < m; i += NT)
            if (g_mk[i] < kf) of[g_mi[i]] = 0.0f;
        __syncthreads();
        if (threadIdx.x == 0) {
            g_ctr[0] = 0; g_ctr[1] = 0;
            g_nscratch = 0; g_overflow = 0; g_mcnt = 0;
        }
        return;
    }

    if (mode == 1) {
        // ---- Fallback: 3 full-read hist phases (12+12+8 bits), spins ----
#define FB_HIST(SDP, DMASK, PREF_SH)                                          \
        {                                                                     \
            const unsigned pref = *(volatile unsigned*)&g_pref;               \
            for (int i = tid; i < n0; i += stride) {                          \
                uint4 v = __ldcs(&a0[i]);                                     \
                unsigned kk[4] = {fmap_u(v.x), fmap_u(v.y),                   \
                                  fmap_u(v.z), fmap_u(v.w)};                  \
                for (int q = 0; q < 4; q++)                                   \
                    if ((PREF_SH) < 0 || (kk[q] >> (PREF_SH)) == pref)        \
                        atomicAdd(&shh[(kk[q] >> (SDP)) & (DMASK)], 1u);      \
            }                                                                 \
            for (int i = tid; i < n1; i += stride) {                          \
                uint4 v = __ldcs(&a1[i]);                                     \
                unsigned kk[4] = {fmap_u(v.x), fmap_u(v.y),                   \
                                  fmap_u(v.z), fmap_u(v.w)};                  \
                for (int q = 0; q < 4; q++)                                   \
                    if ((PREF_SH) < 0 || (kk[q] >> (PREF_SH)) == pref)        \
                        atomicAdd(&shh[(kk[q] >> (SDP)) & (DMASK)], 1u);      \
            }                                                                 \
            for (int i = tid; i < n2; i += stride) {                          \
                uint4 v = __ldcs(&a2[i]);                                     \
                unsigned kk[4] = {fmap_u(v.x), fmap_u(v.y),                   \
                                  fmap_u(v.z), fmap_u(v.w)};                  \
                for (int q = 0; q < 4; q++)                                   \
                    if ((PREF_SH) < 0 || (kk[q] >> (PREF_SH)) == pref)        \
                        atomicAdd(&shh[(kk[q] >> (SDP)) & (DMASK)], 1u);      \
            }                                                                 \
        }
        if (threadIdx.x == 0 && blockIdx.x == 0) g_pref = 0;  // clean prefix
        for (int j = threadIdx.x; j < HBINS; j += NT) shh[j] = 0;
        __syncthreads();
        FB_HIST(20, 4095u, -1)
        __syncthreads();
        for (int j = threadIdx.x; j < HBINS; j += NT)
            if (shh[j]) atomicAdd(&g_h[j], shh[j]);
        fb_sync(3, 4096, 12, 0);

        for (int j = threadIdx.x; j < HBINS; j += NT) shh[j] = 0;
        __syncthreads();
        FB_HIST(8, 4095u, 20)
        __syncthreads();
        for (int j = threadIdx.x; j < HBINS; j += NT)
            if (shh[j]) atomicAdd(&g_h[j], shh[j]);
        fb_sync(4, 4096, 12, 0);

        for (int j = threadIdx.x; j < 256; j += NT) shh[j] = 0;
        __syncthreads();
        FB_HIST(0, 255u, 8)
        __syncthreads();
        for (int j = threadIdx.x; j < 256; j += NT)
            if (shh[j]) atomicAdd(&g_h[j], shh[j]);
        fb_sync(5, 256, 8, 1);
#undef FB_HIST
    }

    // ---- Full rewrite (mode 1 after select, or mode 2 with thresh=0) ----
    {
        const float th = *(volatile float*)&g_thresh;
        const float4* f0 = (const float4*)a0;
        const float4* f1 = (const float4*)a1;
        const float4* f2 = (const float4*)a2;
        for (int i = tid; i < n0; i += stride) {
            float4 v = f0[i];
            v.x = (v.x < th) ? 0.0f : v.x;  v.y = (v.y < th) ? 0.0f : v.y;
            v.z = (v.z < th) ? 0.0f : v.z;  v.w = (v.w < th) ? 0.0f : v.w;
            out[i] = v;
        }
        float4* o1 = out + n0;
        for (int i = tid; i < n1; i += stride) {
            float4 v = f1[i];
            v.x = (v.x < th) ? 0.0f : v.x;  v.y = (v.y < th) ? 0.0f : v.y;
            v.z = (v.z < th) ? 0.0f : v.z;  v.w = (v.w < th) ? 0.0f : v.w;
            o1[i] = v;
        }
        float4* o2 = out + n0 + n1;
        for (int i = tid; i < n2; i += stride) {
            float4 v = f2[i];
            v.x = (v.x < th) ? 0.0f : v.x;  v.y = (v.y < th) ? 0.0f : v.y;
            v.z = (v.z < th) ? 0.0f : v.z;  v.w = (v.w < th) ? 0.0f : v.w;
            o2[i] = v;
        }
    }
    // Epilogue (fallback/trivial): last block resets all replay state.
    __threadfence();
    __syncthreads();
    if (threadIdx.x == 0) {
        if (atomicAdd(&g_ctr[2], 1u) == gridDim.x - 1u) {
            g_ctr[0] = 0; g_ctr[1] = 0; g_ctr[2] = 0;
            g_ctr[3] = 0; g_ctr[4] = 0; g_ctr[5] = 0;
            g_go[3] = 0; g_go[4] = 0; g_go[5] = 0;
            g_nscratch = 0; g_overflow = 0; g_mcnt = 0;
        }
    }
}

// ============================================================================
extern "C" void kernel_launch(void* const* d_in, const int* in_sizes, int n_in,
                              void* d_out, int out_size) {
    const float* e  = (const float*)d_in[0];
    const float* m  = (const float*)d_in[1];
    const float* dp = (const float*)d_in[2];
    const int* mf_ptr = (n_in >= 4) ? (const int*)d_in[3] : nullptr;
    int ne = in_sizes[0], nm = in_sizes[1], nd = in_sizes[2];
    long long ntot = (long long)ne + (long long)nm + (long long)nd;
    int ne4 = ne / 4, nm4 = nm / 4, nd4 = nd / 4;

    const uint4* u0 = (const uint4*)e;
    const uint4* u1 = (const uint4*)m;
    const uint4* u2 = (const uint4*)dp;

    k_pass1<<<NB, NT>>>(u0, ne4, u1, nm4, u2, nd4, (uint4*)d_out,
                        mf_ptr, 500000, ntot);
    k_round2<<<NB, NT>>>(u0, ne4, u1, nm4, u2, nd4, (float4*)d_out);
}